// round 6
// baseline (speedup 1.0000x reference)
#include <cuda_runtime.h>

// MN neuron scan: T=1000 steps, B*N = 32768 independent neurons.
// One thread per neuron; state in registers; depth-10 register prefetch of x.
// All arithmetic uses __f*_rn intrinsics to forbid FMA contraction and match
// XLA's uncontracted per-op IEEE fp32 semantics (spike trains are rounding-
// sensitive: one flipped threshold crossing diverges the neuron's trajectory).

#define T_STEPS 1000
#define NN      512
#define BN      32768   // B * N
#define UPF     10      // prefetch depth (divides T_STEPS)

__global__ __launch_bounds__(128)
void mn_neuron_kernel(const float* __restrict__ x,
                      const float* __restrict__ lin,
                      const float* __restrict__ aarr,
                      const float* __restrict__ A1arr,
                      const float* __restrict__ A2arr,
                      float* __restrict__ out)
{
    const int idx = blockIdx.x * blockDim.x + threadIdx.x;  // neuron id in [0, BN)
    const int n   = idx & (NN - 1);

    // Per-neuron parameters (read once)
    const float lw  = lin[n];
    const float av  = aarr[n];
    const float A1v = A1arr[n];
    const float A2v = A2arr[n];

    // Constants (exact fp32 of the reference doubles)
    const float EL   = -0.07f;
    const float VR   = -0.07f;
    const float TR   = -0.06f;
    const float TINF = -0.05f;
    const float DT   = 0.01f;
    const float K1   = 200.0f;
    const float K2   = 20.0f;
    const float Gc   = 45.24007797241211f;
    const float Bc   = 12.77495288848877f;
    const float R1   = 0.3858567178249359f;
    const float R2   = -1.1421641111373901f;

    // State
    float V   = EL;
    float i1  = 0.0f;
    float i2  = 0.0f;
    float Thr = TINF;

    const float* xp = x + idx;
    float*       op = out + idx;

    // Prime prefetch buffer
    float buf[UPF];
#pragma unroll
    for (int u = 0; u < UPF; ++u)
        buf[u] = xp[(size_t)u * BN];

    for (int t0 = 0; t0 < T_STEPS; t0 += UPF) {
        float cur[UPF];
#pragma unroll
        for (int u = 0; u < UPF; ++u) cur[u] = buf[u];

        // Prefetch next group (10 LDGs in flight while we compute 10 steps)
        if (t0 + UPF < T_STEPS) {
            const float* np = xp + (size_t)(t0 + UPF) * BN;
#pragma unroll
            for (int u = 0; u < UPF; ++u)
                buf[u] = np[(size_t)u * BN];
        }

#pragma unroll
        for (int u = 0; u < UPF; ++u) {
            const float xt = cur[u];

            // i1 = i1 - (K1*i1)*DT ; i2 = i2 - (K2*i2)*DT
            i1 = __fsub_rn(i1, __fmul_rn(__fmul_rn(K1, i1), DT));
            i2 = __fsub_rn(i2, __fmul_rn(__fmul_rn(K2, i2), DT));

            // V = V + DT * (((lin*xt + i1) + i2) - G*(V-EL))   (/C with C=1 exact)
            float s  = __fadd_rn(__fadd_rn(__fmul_rn(lw, xt), i1), i2);
            float gq = __fmul_rn(Gc, __fsub_rn(V, EL));
            V = __fadd_rn(V, __fmul_rn(DT, __fsub_rn(s, gq)));

            // Thr = Thr + DT * (a*(V-EL) - B*(Thr-TINF))
            float t1 = __fmul_rn(av, __fsub_rn(V, EL));
            float t2 = __fmul_rn(Bc, __fsub_rn(Thr, TINF));
            Thr = __fadd_rn(Thr, __fmul_rn(DT, __fsub_rn(t1, t2)));

            // spk = (V - Thr) > 0
            const bool p = (__fsub_rn(V, Thr) > 0.0f);

            // Spike resets: (1-spk)*y + spk*z with spk in {0,1} == exact select
            float i1n = __fadd_rn(__fmul_rn(R1, i1), A1v);
            float i2n = __fadd_rn(__fmul_rn(R2, i2), A2v);
            i1  = p ? i1n : i1;
            i2  = p ? i2n : i2;
            Thr = p ? fmaxf(Thr, TR) : Thr;
            V   = p ? VR : V;

            op[(size_t)(t0 + u) * BN] = p ? 1.0f : 0.0f;
        }
    }
}

extern "C" void kernel_launch(void* const* d_in, const int* in_sizes, int n_in,
                              void* d_out, int out_size)
{
    const float* x   = (const float*)d_in[0];  // [T, B, N]
    const float* lin = (const float*)d_in[1];  // [1, N]
    const float* a   = (const float*)d_in[2];  // [1, N]
    const float* A1  = (const float*)d_in[3];  // [1, N]
    const float* A2  = (const float*)d_in[4];  // [1, N]
    float* out = (float*)d_out;                // [T, B, N]

    (void)in_sizes; (void)n_in; (void)out_size;

    mn_neuron_kernel<<<BN / 128, 128>>>(x, lin, a, A1, A2, out);
}

// round 7
// speedup vs baseline: 1.1527x; 1.1527x over previous
#include <cuda_runtime.h>

// MN neuron scan: T=1000 steps, B*N = 32768 independent neurons.
// One thread per neuron; state in registers; depth-10 register prefetch of x.
//
// R6: all arithmetic emitted as fma.rn.f32 via inline asm.
//   a+b  == fma(a, 1.0, b)    (bit-exact: a*1 exact, one rounding)
//   a-b  == fma(b, -1.0, a)
//   a*k  == fma(a, k, -0.0)   (bit-exact incl. signed zero)
// Inline asm blocks NVVM from folding these back to FADD/FMUL; ptxas
// propagates the immediates into FFMA-imm form (rt_SMSP=1 vs 2 for FADD/FMUL),
// doubling scalar-pipe throughput while preserving XLA's uncontracted
// per-op IEEE rounding (spike trains are rounding-sensitive).
// 32-thread blocks give near-perfect wave balance (max 7 warps/SM vs avg 6.92).

#define T_STEPS 1000
#define NN      512
#define BN      32768   // B * N
#define UPF     10      // prefetch depth (divides T_STEPS)

__device__ __forceinline__ float ffma(float a, float b, float c) {
    float d;
    asm("fma.rn.f32 %0, %1, %2, %3;" : "=f"(d) : "f"(a), "f"(b), "f"(c));
    return d;
}

__global__ __launch_bounds__(32)
void mn_neuron_kernel(const float* __restrict__ x,
                      const float* __restrict__ lin,
                      const float* __restrict__ aarr,
                      const float* __restrict__ A1arr,
                      const float* __restrict__ A2arr,
                      float* __restrict__ out)
{
    const int idx = blockIdx.x * blockDim.x + threadIdx.x;  // neuron id in [0, BN)
    const int n   = idx & (NN - 1);

    // Per-neuron parameters (read once)
    const float lw  = lin[n];
    const float av  = aarr[n];
    const float A1v = A1arr[n];
    const float A2v = A2arr[n];

    // Constants (exact fp32 of the reference values)
    const float VR   = -0.07f;
    const float TR   = -0.06f;
    const float NEL  =  0.07f;   // -EL   (V - EL  == V + 0.07)
    const float NTIN =  0.05f;   // -TINF (Thr-TINF== Thr + 0.05)
    const float DT   = 0.01f;
    const float K1   = 200.0f;
    const float K2   = 20.0f;
    const float Gc   = 45.24007797241211f;
    const float Bc   = 12.77495288848877f;
    const float R1   = 0.3858567178249359f;
    const float R2   = -1.1421641111373901f;
    const float NZ   = -0.0f;    // FMUL-equivalent addend

    // State
    float V   = -0.07f;
    float i1  = 0.0f;
    float i2  = 0.0f;
    float Thr = -0.05f;

    const float* xp = x + idx;
    float*       op = out + idx;

    // Prime prefetch buffer (UPF independent loads in flight)
    float buf[UPF];
#pragma unroll
    for (int u = 0; u < UPF; ++u)
        buf[u] = xp[(size_t)u * BN];

    for (int t0 = 0; t0 < T_STEPS; t0 += UPF) {
        float cur[UPF];
#pragma unroll
        for (int u = 0; u < UPF; ++u) cur[u] = buf[u];

        // Prefetch next group while computing this one
        if (t0 + UPF < T_STEPS) {
            const float* np = xp + (size_t)(t0 + UPF) * BN;
#pragma unroll
            for (int u = 0; u < UPF; ++u)
                buf[u] = np[(size_t)u * BN];
        }

#pragma unroll
        for (int u = 0; u < UPF; ++u) {
            const float xt = cur[u];

            // i1 = i1 - (K1*i1)*DT
            float m1 = ffma(i1, K1, NZ);      // rn(K1*i1)
            m1       = ffma(m1, DT, NZ);      // rn(.. * DT)
            i1       = ffma(m1, -1.0f, i1);   // rn(i1 - ..)
            // i2 = i2 - (K2*i2)*DT
            float m2 = ffma(i2, K2, NZ);
            m2       = ffma(m2, DT, NZ);
            i2       = ffma(m2, -1.0f, i2);

            // V = V + DT * (((lin*xt + i1) + i2) - G*(V-EL))
            float lx  = ffma(lw, xt, NZ);     // rn(lin*xt)
            float s   = ffma(lx, 1.0f, i1);   // rn(.. + i1)
            s         = ffma(s,  1.0f, i2);   // rn(.. + i2)
            float vel = ffma(V,  1.0f, NEL);  // rn(V - EL)
            float gq  = ffma(vel, Gc, NZ);    // rn(G*(V-EL))
            float dv  = ffma(gq, -1.0f, s);   // rn(s - gq)
            dv        = ffma(dv, DT, NZ);     // rn(DT * ..)
            V         = ffma(dv, 1.0f, V);    // rn(V + ..)

            // Thr = Thr + DT * (a*(V-EL) - B*(Thr-TINF))
            float ve2 = ffma(V,  1.0f, NEL);  // rn(V - EL)    (new V)
            float t1  = ffma(av, ve2, NZ);    // rn(a * ..)
            float tt  = ffma(Thr, 1.0f, NTIN);// rn(Thr - TINF)
            float t2  = ffma(tt, Bc, NZ);     // rn(B * ..)
            float dd  = ffma(t2, -1.0f, t1);  // rn(t1 - t2)
            dd        = ffma(dd, DT, NZ);     // rn(DT * ..)
            Thr       = ffma(dd, 1.0f, Thr);  // rn(Thr + ..)

            // spk = (V - Thr) > 0
            float vm = ffma(Thr, -1.0f, V);   // rn(V - Thr)
            const bool p = (vm > 0.0f);

            // Resets ((1-spk)*y + spk*z with spk in {0,1} == exact select)
            float i1m = ffma(i1, R1, NZ);     // rn(R1*i1)  (two-rounded, as ref)
            float i1n = ffma(i1m, 1.0f, A1v); // rn(.. + A1)
            float i2m = ffma(i2, R2, NZ);
            float i2n = ffma(i2m, 1.0f, A2v);
            i1  = p ? i1n : i1;
            i2  = p ? i2n : i2;
            Thr = p ? fmaxf(Thr, TR) : Thr;
            V   = p ? VR : V;

            op[(size_t)(t0 + u) * BN] = p ? 1.0f : 0.0f;
        }
    }
}

extern "C" void kernel_launch(void* const* d_in, const int* in_sizes, int n_in,
                              void* d_out, int out_size)
{
    const float* x   = (const float*)d_in[0];  // [T, B, N]
    const float* lin = (const float*)d_in[1];  // [1, N]
    const float* a   = (const float*)d_in[2];  // [1, N]
    const float* A1  = (const float*)d_in[3];  // [1, N]
    const float* A2  = (const float*)d_in[4];  // [1, N]
    float* out = (float*)d_out;                // [T, B, N]

    (void)in_sizes; (void)n_in; (void)out_size;

    mn_neuron_kernel<<<BN / 32, 32>>>(x, lin, a, A1, A2, out);
}

// round 8
// speedup vs baseline: 1.3392x; 1.1618x over previous
#include <cuda_runtime.h>

// MN neuron scan: T=1000 steps, B*N = 32768 independent neurons.
//
// R7: latency-bound recurrence fix.
//  - 2 neurons per thread: two independent dependency chains interleaved in
//    one warp's issue stream -> warp IPC approaches 1 (was ~0.17, issue=30%).
//  - Adjacent-neuron pairing -> float2 loads/stores (LDG.64/STG.64), coalesced.
//  - Depth-20 prefetch (two ping-pong groups of 10) -> issue-to-consume
//    distance ~1200 cycles > ~1050-cycle NAT-clock DRAM latency.
// Arithmetic identical per neuron to R6: every op is fma.rn.f32 via inline asm
// (a+b == fma(a,1,b); a*k == fma(a,k,-0.0); bit-exact, XLA-uncontracted order).

#define T_STEPS 1000
#define NN      512
#define BN      32768          // B * N
#define NT      (BN / 2)       // threads (2 neurons each)
#define UPF     10             // steps per prefetch group

__device__ __forceinline__ float ffma(float a, float b, float c) {
    float d;
    asm("fma.rn.f32 %0, %1, %2, %3;" : "=f"(d) : "f"(a), "f"(b), "f"(c));
    return d;
}

struct NState { float V, i1, i2, Thr; };

// One bit-exact reference step for one neuron. Returns spike (0/1).
__device__ __forceinline__ float step_one(NState& s, float xt,
                                          float lw, float av,
                                          float A1v, float A2v)
{
    const float VR   = -0.07f;
    const float TR   = -0.06f;
    const float NEL  =  0.07f;   // -EL
    const float NTIN =  0.05f;   // -TINF
    const float DT   = 0.01f;
    const float K1   = 200.0f;
    const float K2   = 20.0f;
    const float Gc   = 45.24007797241211f;
    const float Bc   = 12.77495288848877f;
    const float R1   = 0.3858567178249359f;
    const float R2   = -1.1421641111373901f;
    const float NZ   = -0.0f;

    // i1 -= (K1*i1)*DT ; i2 -= (K2*i2)*DT
    float m1 = ffma(s.i1, K1, NZ); m1 = ffma(m1, DT, NZ); s.i1 = ffma(m1, -1.0f, s.i1);
    float m2 = ffma(s.i2, K2, NZ); m2 = ffma(m2, DT, NZ); s.i2 = ffma(m2, -1.0f, s.i2);

    // V += DT * (((lin*xt + i1) + i2) - G*(V-EL))
    float lx  = ffma(lw, xt, NZ);
    float ss  = ffma(lx, 1.0f, s.i1);
    ss        = ffma(ss, 1.0f, s.i2);
    float vel = ffma(s.V, 1.0f, NEL);
    float gq  = ffma(vel, Gc, NZ);
    float dv  = ffma(gq, -1.0f, ss);
    dv        = ffma(dv, DT, NZ);
    s.V       = ffma(dv, 1.0f, s.V);

    // Thr += DT * (a*(V-EL) - B*(Thr-TINF))
    float ve2 = ffma(s.V, 1.0f, NEL);
    float t1  = ffma(av, ve2, NZ);
    float tt  = ffma(s.Thr, 1.0f, NTIN);
    float t2  = ffma(tt, Bc, NZ);
    float dd  = ffma(t2, -1.0f, t1);
    dd        = ffma(dd, DT, NZ);
    s.Thr     = ffma(dd, 1.0f, s.Thr);

    // spk = (V - Thr) > 0
    float vm = ffma(s.Thr, -1.0f, s.V);
    const bool p = (vm > 0.0f);

    // resets (spk in {0,1} -> exact selects)
    float i1n = ffma(ffma(s.i1, R1, NZ), 1.0f, A1v);
    float i2n = ffma(ffma(s.i2, R2, NZ), 1.0f, A2v);
    s.i1  = p ? i1n : s.i1;
    s.i2  = p ? i2n : s.i2;
    s.Thr = p ? fmaxf(s.Thr, TR) : s.Thr;
    s.V   = p ? VR : s.V;
    return p ? 1.0f : 0.0f;
}

__global__ __launch_bounds__(32)
void mn_neuron_kernel(const float* __restrict__ x,
                      const float* __restrict__ lin,
                      const float* __restrict__ aarr,
                      const float* __restrict__ A1arr,
                      const float* __restrict__ A2arr,
                      float* __restrict__ out)
{
    const int gid = blockIdx.x * 32 + threadIdx.x;   // pair id in [0, NT)
    const int n0  = (2 * gid) & (NN - 1);            // even; n1 = n0+1

    // Parameters for the pair (vectorized; n0 even -> 8B aligned)
    const float2 l2  = *(const float2*)(lin   + n0);
    const float2 a2  = *(const float2*)(aarr  + n0);
    const float2 A12 = *(const float2*)(A1arr + n0);
    const float2 A22 = *(const float2*)(A2arr + n0);

    NState s0 = { -0.07f, 0.0f, 0.0f, -0.05f };
    NState s1 = { -0.07f, 0.0f, 0.0f, -0.05f };

    const float2* xp = (const float2*)x   + gid;     // stride BN/2 float2 per step
    float2*       op = (float2*)      out + gid;

    // Prime two prefetch groups (20 LDG.64 in flight, ~20-step distance)
    float2 bufA[UPF], bufB[UPF];
#pragma unroll
    for (int u = 0; u < UPF; ++u) bufA[u] = xp[(size_t)u * (BN / 2)];
#pragma unroll
    for (int u = 0; u < UPF; ++u) bufB[u] = xp[(size_t)(UPF + u) * (BN / 2)];

    for (int t0 = 0; t0 < T_STEPS; t0 += 2 * UPF) {
        // ---- phase A: consume bufA (steps t0 .. t0+UPF-1) ----
        float2 cur[UPF];
#pragma unroll
        for (int u = 0; u < UPF; ++u) cur[u] = bufA[u];
        if (t0 + 2 * UPF < T_STEPS) {
            const float2* np = xp + (size_t)(t0 + 2 * UPF) * (BN / 2);
#pragma unroll
            for (int u = 0; u < UPF; ++u) bufA[u] = np[(size_t)u * (BN / 2)];
        }
#pragma unroll
        for (int u = 0; u < UPF; ++u) {
            float2 sp;
            sp.x = step_one(s0, cur[u].x, l2.x, a2.x, A12.x, A22.x);
            sp.y = step_one(s1, cur[u].y, l2.y, a2.y, A12.y, A22.y);
            op[(size_t)(t0 + u) * (BN / 2)] = sp;
        }

        // ---- phase B: consume bufB (steps t0+UPF .. t0+2*UPF-1) ----
#pragma unroll
        for (int u = 0; u < UPF; ++u) cur[u] = bufB[u];
        if (t0 + 3 * UPF < T_STEPS) {
            const float2* np = xp + (size_t)(t0 + 3 * UPF) * (BN / 2);
#pragma unroll
            for (int u = 0; u < UPF; ++u) bufB[u] = np[(size_t)u * (BN / 2)];
        }
#pragma unroll
        for (int u = 0; u < UPF; ++u) {
            float2 sp;
            sp.x = step_one(s0, cur[u].x, l2.x, a2.x, A12.x, A22.x);
            sp.y = step_one(s1, cur[u].y, l2.y, a2.y, A12.y, A22.y);
            op[(size_t)(t0 + UPF + u) * (BN / 2)] = sp;
        }
    }
}

extern "C" void kernel_launch(void* const* d_in, const int* in_sizes, int n_in,
                              void* d_out, int out_size)
{
    const float* x   = (const float*)d_in[0];  // [T, B, N]
    const float* lin = (const float*)d_in[1];  // [1, N]
    const float* a   = (const float*)d_in[2];  // [1, N]
    const float* A1  = (const float*)d_in[3];  // [1, N]
    const float* A2  = (const float*)d_in[4];  // [1, N]
    float* out = (float*)d_out;                // [T, B, N]

    (void)in_sizes; (void)n_in; (void)out_size;

    mn_neuron_kernel<<<NT / 32, 32>>>(x, lin, a, A1, A2, out);
}